// round 8
// baseline (speedup 1.0000x reference)
#include <cuda_runtime.h>
#include <math.h>

#define DIM        768
#define NUM_CLASS  1024
#define INST       64
#define ROWS_PB    32                          // rows per block (half class)
#define NBLK_MAIN  (3 * NUM_CLASS * 2)         // 6144
#define NPAIR      (3 * NUM_CLASS)             // 3072
#define D4         (DIM / 4)                   // 192 float4 per S row
#define F4MOD      (NUM_CLASS * D4)            // 196608 f4 per modality
#define F4HALF     (F4MOD / 2)                 // 98304
#define BLK_PER_M  384                         // 384*256 = 98304 threads
#define NBLK_LOSS  (3 * BLK_PER_M)             // 1152
#define SMEM_MAIN  (ROWS_PB * DIM * sizeof(float))  // 98304 B

// Planar half-S tables: g_Sa = half 0, g_Sb = half 1, indexed [pair*DIM + d].
// Plain stores; every slot fully written each call (no pre-zero needed).
__device__ float    g_Sa[NPAIR * DIM];
__device__ float    g_Sb[NPAIR * DIM];
__device__ double   g_acc;
__device__ unsigned g_done;   // zero at load; finalizer resets each call

// ---------------------------------------------------------------------------
// Kernel 1: normalize rows + per-half column sums (the only HBM-heavy pass)
// ---------------------------------------------------------------------------
__global__ __launch_bounds__(1024, 2)
void main_kernel(const float* __restrict__ rgb,
                 const float* __restrict__ nir,
                 const float* __restrict__ tir) {
    extern __shared__ float sm[];              // [ROWS_PB][DIM]

    if (blockIdx.x == 0 && threadIdx.x == 0) g_acc = 0.0;  // in-stream before loss

    const int b    = blockIdx.x;               // 0..6143
    const int pair = b >> 1;                   // (m,c): m = pair>>10, c = pair&1023
    const int half = b & 1;
    const int m    = pair >> 10;
    const int c    = pair & (NUM_CLASS - 1);

    const float* feat = (m == 0) ? rgb : (m == 1) ? nir : tir;
    const int row0 = c * INST + half * ROWS_PB;

    const int w = threadIdx.x >> 5;            // warp id = local row
    const int l = threadIdx.x & 31;            // lane

    const float4* src = (const float4*)(feat + (size_t)(row0 + w) * DIM);

    float4 v[6];
    float ss = 0.0f;
#pragma unroll
    for (int k = 0; k < 6; k++) {
        v[k] = __ldcs(&src[k * 32 + l]);       // streaming: data read once
        ss += v[k].x * v[k].x + v[k].y * v[k].y
            + v[k].z * v[k].z + v[k].w * v[k].w;
    }
#pragma unroll
    for (int o = 16; o; o >>= 1)
        ss += __shfl_xor_sync(0xffffffffu, ss, o);

    const float invn = 1.0f / fmaxf(sqrtf(ss), 1e-12f);

    float4* dst = (float4*)(sm + w * DIM);
#pragma unroll
    for (int k = 0; k < 6; k++) {
        float4 t = v[k];
        t.x *= invn; t.y *= invn; t.z *= invn; t.w *= invn;
        dst[k * 32 + l] = t;
    }
    __syncthreads();

    if (threadIdx.x < DIM) {
        float acc = 0.0f;
#pragma unroll 8
        for (int r = 0; r < ROWS_PB; r++)
            acc += sm[r * DIM + threadIdx.x];
        float* table = half ? g_Sb : g_Sa;
        table[(size_t)pair * DIM + threadIdx.x] = acc;
    }
}

// ---------------------------------------------------------------------------
// Kernel 2: loss as three pure linear streams. Block-uniform modality.
//   g = global f4 index;  s = Sa[g]+Sb[g];  o = cen_m[g - m*F4MOD]
//   nc = 0.0125*s + 0.2*o;  term = 64*nc^2 - 2*nc*s
//   loss = (Σ term + 3*B) / (B*D)
// ---------------------------------------------------------------------------
__global__ __launch_bounds__(256)
void loss_kernel(const float* __restrict__ cr,
                 const float* __restrict__ cn,
                 const float* __restrict__ ct,
                 float* __restrict__ out) {
    const float4* Sa4 = (const float4*)g_Sa;
    const float4* Sb4 = (const float4*)g_Sb;

    const int mb = blockIdx.x / BLK_PER_M;            // modality (block-uniform)
    const int lb = blockIdx.x - mb * BLK_PER_M;       // 0..383
    const float4* cen4 = (const float4*)((mb == 0) ? cr : (mb == 1) ? cn : ct);

    const int e0 = lb * 256 + threadIdx.x;            // [0, 98304)
    const int e1 = e0 + F4HALF;                       // [98304, 196608)
    const int g0 = mb * F4MOD + e0;
    const int g1 = mb * F4MOD + e1;

    // six independent linear LDG.128s
    float4 a0 = Sa4[g0];
    float4 b0 = Sb4[g0];
    float4 o0 = __ldg(&cen4[e0]);
    float4 a1 = Sa4[g1];
    float4 b1 = Sb4[g1];
    float4 o1 = __ldg(&cen4[e1]);

    float partial = 0.0f;
    {
        float s0 = a0.x + b0.x, s1 = a0.y + b0.y, s2 = a0.z + b0.z, s3 = a0.w + b0.w;
        float n0 = 0.0125f * s0 + 0.2f * o0.x;
        float n1 = 0.0125f * s1 + 0.2f * o0.y;
        float n2 = 0.0125f * s2 + 0.2f * o0.z;
        float n3 = 0.0125f * s3 + 0.2f * o0.w;
        partial += 64.0f * n0 * n0 - 2.0f * n0 * s0;
        partial += 64.0f * n1 * n1 - 2.0f * n1 * s1;
        partial += 64.0f * n2 * n2 - 2.0f * n2 * s2;
        partial += 64.0f * n3 * n3 - 2.0f * n3 * s3;
    }
    {
        float s0 = a1.x + b1.x, s1 = a1.y + b1.y, s2 = a1.z + b1.z, s3 = a1.w + b1.w;
        float n0 = 0.0125f * s0 + 0.2f * o1.x;
        float n1 = 0.0125f * s1 + 0.2f * o1.y;
        float n2 = 0.0125f * s2 + 0.2f * o1.z;
        float n3 = 0.0125f * s3 + 0.2f * o1.w;
        partial += 64.0f * n0 * n0 - 2.0f * n0 * s0;
        partial += 64.0f * n1 * n1 - 2.0f * n1 * s1;
        partial += 64.0f * n2 * n2 - 2.0f * n2 * s2;
        partial += 64.0f * n3 * n3 - 2.0f * n3 * s3;
    }

    // block reduce (256 threads)
    __shared__ float red[8];
#pragma unroll
    for (int o = 16; o; o >>= 1)
        partial += __shfl_xor_sync(0xffffffffu, partial, o);
    if ((threadIdx.x & 31) == 0) red[threadIdx.x >> 5] = partial;
    __syncthreads();

    if (threadIdx.x == 0) {
        float v = 0.0f;
#pragma unroll
        for (int i = 0; i < 8; i++) v += red[i];
        atomicAdd(&g_acc, (double)v);

        __threadfence();
        unsigned old = atomicAdd(&g_done, 1u);
        if (old == NBLK_LOSS - 1) {            // last block: finalize + clean
            double a = atomicAdd(&g_acc, 0.0);
            const double B = (double)(NUM_CLASS * INST);    // 65536
            out[0] = (float)((a + 3.0 * B) / (B * (double)DIM));
            g_done = 0u;
        }
    }
}

// ---------------------------------------------------------------------------
extern "C" void kernel_launch(void* const* d_in, const int* in_sizes, int n_in,
                              void* d_out, int out_size) {
    const float* rgb = (const float*)d_in[0];
    const float* nir = (const float*)d_in[1];
    const float* tir = (const float*)d_in[2];
    const float* cr  = (const float*)d_in[3];
    const float* cn  = (const float*)d_in[4];
    const float* ct  = (const float*)d_in[5];
    float* out = (float*)d_out;

    cudaFuncSetAttribute(main_kernel,
                         cudaFuncAttributeMaxDynamicSharedMemorySize,
                         (int)SMEM_MAIN);

    main_kernel<<<NBLK_MAIN, 1024, SMEM_MAIN>>>(rgb, nir, tir);
    loss_kernel<<<NBLK_LOSS, 256>>>(cr, cn, ct, out);
}

// round 9
// speedup vs baseline: 1.0316x; 1.0316x over previous
#include <cuda_runtime.h>
#include <math.h>

#define DIM        768
#define NUM_CLASS  1024
#define INST       64
#define ROWS_PB    32                         // rows per block (half class)
#define NBLK_MAIN  (3 * NUM_CLASS * 2)        // 6144
#define NPAIR      (3 * NUM_CLASS)            // 3072
#define D4         (DIM / 4)                  // 192 float4 per S row
#define N4TOT      (NPAIR * D4)               // 589824 items
#define NBLK_LOSS  296                        // 2 per SM, one wave
#define NTHR_LOSS  1024
#define LSTRIDE    (NBLK_LOSS * NTHR_LOSS)    // 303104
#define SMEM_MAIN  (ROWS_PB * DIM * sizeof(float))  // 98304 B

// Per-(modality,class,half) column sums of normalized rows (R4 layout).
// Plain stores; every slot fully written each call (no pre-zero).
__device__ float    g_S2[NBLK_MAIN * DIM];
__device__ double   g_acc;
__device__ unsigned g_done;   // zero at load; finalizer resets each call

// ---------------------------------------------------------------------------
// Kernel 1: normalize rows + per-half column sums (identical to R4 best)
// ---------------------------------------------------------------------------
__global__ __launch_bounds__(1024, 2)
void main_kernel(const float* __restrict__ rgb,
                 const float* __restrict__ nir,
                 const float* __restrict__ tir) {
    extern __shared__ float sm[];             // [ROWS_PB][DIM]

    if (blockIdx.x == 0 && threadIdx.x == 0) g_acc = 0.0;  // in-stream before loss

    const int b    = blockIdx.x;              // 0..6143
    const int m    = b >> 11;
    const int rem  = b & 2047;
    const int c    = rem >> 1;
    const int half = rem & 1;

    const float* feat = (m == 0) ? rgb : (m == 1) ? nir : tir;
    const int row0 = c * INST + half * ROWS_PB;

    const int w = threadIdx.x >> 5;           // warp id = local row
    const int l = threadIdx.x & 31;           // lane

    const float4* src = (const float4*)(feat + (size_t)(row0 + w) * DIM);

    float4 v[6];
    float ss = 0.0f;
#pragma unroll
    for (int k = 0; k < 6; k++) {
        v[k] = __ldcs(&src[k * 32 + l]);      // streaming: data read once
        ss += v[k].x * v[k].x + v[k].y * v[k].y
            + v[k].z * v[k].z + v[k].w * v[k].w;
    }
#pragma unroll
    for (int o = 16; o; o >>= 1)
        ss += __shfl_xor_sync(0xffffffffu, ss, o);

    const float invn = 1.0f / fmaxf(sqrtf(ss), 1e-12f);

    float4* dst = (float4*)(sm + w * DIM);
#pragma unroll
    for (int k = 0; k < 6; k++) {
        float4 t = v[k];
        t.x *= invn; t.y *= invn; t.z *= invn; t.w *= invn;
        dst[k * 32 + l] = t;
    }
    __syncthreads();

    if (threadIdx.x < DIM) {
        float acc = 0.0f;
#pragma unroll 8
        for (int r = 0; r < ROWS_PB; r++)
            acc += sm[r * DIM + threadIdx.x];
        g_S2[(size_t)b * DIM + threadIdx.x] = acc;
    }
}

// ---------------------------------------------------------------------------
// Kernel 2: loss. 296 wide blocks, 2 items/thread, ONE atomic per block.
//   item e -> pair p = e/192, q = e%192 ; s = h0[q]+h1[q]
//   nc = 0.0125*s + 0.2*old ; term = 64*nc^2 - 2*nc*s
//   loss = (Σ term + 3*B) / (B*D)
// ---------------------------------------------------------------------------
__global__ __launch_bounds__(NTHR_LOSS)
void loss_kernel(const float* __restrict__ cr,
                 const float* __restrict__ cn,
                 const float* __restrict__ ct,
                 float* __restrict__ out) {
    const float4* S4 = (const float4*)g_S2;

    float partial = 0.0f;

#pragma unroll
    for (int it = 0; it < 2; it++) {
        const int e = it * LSTRIDE + blockIdx.x * NTHR_LOSS + threadIdx.x;
        if (e < N4TOT) {
            const int p = e / D4;             // pair (m,c)
            const int q = e - p * D4;
            const int m = p >> 10;
            const int c = p & (NUM_CLASS - 1);
            const float* cen = (m == 0) ? cr : (m == 1) ? cn : ct;

            float4 a  = S4[(size_t)(2 * p + 0) * D4 + q];
            float4 bb = S4[(size_t)(2 * p + 1) * D4 + q];
            float4 o  = __ldg(&((const float4*)cen)[(size_t)c * D4 + q]);

            float s0 = a.x + bb.x, s1 = a.y + bb.y;
            float s2 = a.z + bb.z, s3 = a.w + bb.w;
            float n0 = 0.0125f * s0 + 0.2f * o.x;
            float n1 = 0.0125f * s1 + 0.2f * o.y;
            float n2 = 0.0125f * s2 + 0.2f * o.z;
            float n3 = 0.0125f * s3 + 0.2f * o.w;
            partial += 64.0f * n0 * n0 - 2.0f * n0 * s0;
            partial += 64.0f * n1 * n1 - 2.0f * n1 * s1;
            partial += 64.0f * n2 * n2 - 2.0f * n2 * s2;
            partial += 64.0f * n3 * n3 - 2.0f * n3 * s3;
        }
    }

    // block reduce (1024 threads) -> single atomic
    __shared__ float red[32];
#pragma unroll
    for (int o = 16; o; o >>= 1)
        partial += __shfl_xor_sync(0xffffffffu, partial, o);
    if ((threadIdx.x & 31) == 0) red[threadIdx.x >> 5] = partial;
    __syncthreads();

    if (threadIdx.x < 32) {
        float v = red[threadIdx.x];
#pragma unroll
        for (int o = 16; o; o >>= 1)
            v += __shfl_xor_sync(0xffffffffu, v, o);
        if (threadIdx.x == 0) {
            atomicAdd(&g_acc, (double)v);
            __threadfence();
            unsigned old = atomicAdd(&g_done, 1u);
            if (old == NBLK_LOSS - 1) {       // last block: finalize + clean
                double a = atomicAdd(&g_acc, 0.0);
                const double B = (double)(NUM_CLASS * INST);   // 65536
                out[0] = (float)((a + 3.0 * B) / (B * (double)DIM));
                g_done = 0u;
            }
        }
    }
}

// ---------------------------------------------------------------------------
extern "C" void kernel_launch(void* const* d_in, const int* in_sizes, int n_in,
                              void* d_out, int out_size) {
    const float* rgb = (const float*)d_in[0];
    const float* nir = (const float*)d_in[1];
    const float* tir = (const float*)d_in[2];
    const float* cr  = (const float*)d_in[3];
    const float* cn  = (const float*)d_in[4];
    const float* ct  = (const float*)d_in[5];
    float* out = (float*)d_out;

    cudaFuncSetAttribute(main_kernel,
                         cudaFuncAttributeMaxDynamicSharedMemorySize,
                         (int)SMEM_MAIN);

    main_kernel<<<NBLK_MAIN, 1024, SMEM_MAIN>>>(rgb, nir, tir);
    loss_kernel<<<NBLK_LOSS, NTHR_LOSS>>>(cr, cn, ct, out);
}